// round 1
// baseline (speedup 1.0000x reference)
#include <cuda_runtime.h>
#include <cstddef>
#include <cstdint>

#define SEQ   512
#define BATCH 256
#define INP   256
#define HID   512

typedef unsigned long long u64;

// ---------- packed f32x2 helpers (sm_103a) ----------
__device__ __forceinline__ u64 dup2(float x) {
    u64 r; asm("mov.b64 %0,{%1,%1};" : "=l"(r) : "f"(x)); return r;
}
__device__ __forceinline__ void fma2(u64& d, u64 a, u64 b) {
    asm("fma.rn.f32x2 %0,%1,%2,%0;" : "+l"(d) : "l"(a), "l"(b));
}
__device__ __forceinline__ float2 upk(u64 v) {
    float2 f; asm("mov.b64 {%0,%1},%2;" : "=f"(f.x), "=f"(f.y) : "l"(v)); return f;
}

// ---------- scratch (device globals: allocation-free) ----------
// XP[m][1536]: m = s*BATCH+b ; cols [0:512)=xc, [512:1024)=xa, [1024:1536)=xh
__device__ float g_xp[(size_t)SEQ * BATCH * 3 * HID];   // 805 MB
__device__ float g_h[2][BATCH * HID];                   // double-buffered hidden state
__device__ unsigned          g_cnt[8 * 32];             // per-batch-tile barrier counters
__device__ volatile unsigned g_gen[8 * 32];             // per-batch-tile barrier generations

// ============================================================================
// Projection GEMM:  XP[m][n] = dot(X[m][:], U_sel[n%512][:]) + bias_sel[n%512]
// M=131072, K=256, N=1536. BM=128, BN=128, BK=16, 256 threads, 8x8/thread,
// f32x2-packed over the n dimension.
// ============================================================================
__global__ void __launch_bounds__(256) proj_kernel(
    const float* __restrict__ X,
    const float* __restrict__ Uc, const float* __restrict__ bc,
    const float* __restrict__ Ua, const float* __restrict__ ba,
    const float* __restrict__ Uh, const float* __restrict__ bh)
{
    __shared__ __align__(16) float As[16][128];   // As[k][m]
    __shared__ __align__(16) float Bs[16][128];   // Bs[k][n]

    const int nt = blockIdx.x;            // 0..11
    const int mt = blockIdx.y;            // 0..1023
    const int n0 = nt * 128, m0 = mt * 128;
    const int region = n0 >> 9;           // 0=c, 1=a, 2=h
    const float* __restrict__ U    = (region == 0) ? Uc : (region == 1 ? Ua : Uh);
    const float* __restrict__ bias = (region == 0) ? bc : (region == 1 ? ba : bh);
    const int nl0 = n0 & 511;

    const int tid = threadIdx.x;
    const int tn = tid & 15;              // n-thread (8 n each)
    const int tm = tid >> 4;              // m-thread (8 m each)
    const int lr = tid & 127;             // load row
    const int lc = tid >> 7;              // load col group (0..1)

    u64 acc[8][4];
    #pragma unroll
    for (int i = 0; i < 8; i++)
        #pragma unroll
        for (int q = 0; q < 4; q++) acc[i][q] = 0ull;

    for (int kt = 0; kt < 16; kt++) {
        const int k0 = kt * 16;
        // load A tile (128m x 16k), transposed into As[k][m]  (conflict-free STS)
        #pragma unroll
        for (int half = 0; half < 2; half++) {
            int c = lc + 2 * half;        // float4 index along k (0..3)
            float4 v = *(const float4*)&X[(size_t)(m0 + lr) * INP + k0 + c * 4];
            As[c * 4 + 0][lr] = v.x; As[c * 4 + 1][lr] = v.y;
            As[c * 4 + 2][lr] = v.z; As[c * 4 + 3][lr] = v.w;
        }
        // load B tile (128n x 16k) from U rows, transposed into Bs[k][n]
        #pragma unroll
        for (int half = 0; half < 2; half++) {
            int c = lc + 2 * half;
            float4 v = *(const float4*)&U[(size_t)(nl0 + lr) * INP + k0 + c * 4];
            Bs[c * 4 + 0][lr] = v.x; Bs[c * 4 + 1][lr] = v.y;
            Bs[c * 4 + 2][lr] = v.z; Bs[c * 4 + 3][lr] = v.w;
        }
        __syncthreads();

        #pragma unroll
        for (int k = 0; k < 16; k++) {
            float4 a0 = *(const float4*)&As[k][tm * 8];
            float4 a1 = *(const float4*)&As[k][tm * 8 + 4];
            ulonglong2 b0 = *(const ulonglong2*)&Bs[k][tn * 8];
            ulonglong2 b1 = *(const ulonglong2*)&Bs[k][tn * 8 + 4];
            u64 ad[8];
            ad[0] = dup2(a0.x); ad[1] = dup2(a0.y); ad[2] = dup2(a0.z); ad[3] = dup2(a0.w);
            ad[4] = dup2(a1.x); ad[5] = dup2(a1.y); ad[6] = dup2(a1.z); ad[7] = dup2(a1.w);
            #pragma unroll
            for (int i = 0; i < 8; i++) {
                fma2(acc[i][0], ad[i], b0.x);
                fma2(acc[i][1], ad[i], b0.y);
                fma2(acc[i][2], ad[i], b1.x);
                fma2(acc[i][3], ad[i], b1.y);
            }
        }
        __syncthreads();
    }

    float bv[8];
    #pragma unroll
    for (int q = 0; q < 8; q++) bv[q] = bias[nl0 + tn * 8 + q];
    #pragma unroll
    for (int i = 0; i < 8; i++) {
        const size_t m = (size_t)m0 + tm * 8 + i;
        float2 p0 = upk(acc[i][0]), p1 = upk(acc[i][1]);
        float2 p2 = upk(acc[i][2]), p3 = upk(acc[i][3]);
        float4 o0 = make_float4(p0.x + bv[0], p0.y + bv[1], p1.x + bv[2], p1.y + bv[3]);
        float4 o1 = make_float4(p2.x + bv[4], p2.y + bv[5], p3.x + bv[6], p3.y + bv[7]);
        float* dst = &g_xp[m * 1536 + n0 + tn * 8];
        *(float4*)dst       = o0;
        *(float4*)(dst + 4) = o1;
    }
}

// ============================================================================
// Persistent recurrence kernel.
// Grid = 128 CTAs: 16 hidden tiles (32 j) x 8 batch tiles (32 b).
// W_c/W_a slices (transposed) live in SMEM for all 512 steps.
// h exchanged through global double buffer; 16-way barrier per batch tile.
// ============================================================================
#define HSTRIDE 516   // padded row stride for Hs (avoid bank conflicts)

__global__ void __launch_bounds__(256) recur_kernel(
    const float* __restrict__ h_in,
    const float* __restrict__ Wc, const float* __restrict__ Wa,
    float* __restrict__ out)
{
    extern __shared__ float sm[];
    float* WcT = sm;                          // [512][32]  (k-major, transposed)
    float* WaT = sm + 512 * 32;               // [512][32]
    float* Hs  = sm + 2 * 512 * 32;           // [32][HSTRIDE]

    const int ct = blockIdx.x;                // 0..127
    const int jt = ct & 15, bt = ct >> 4;
    const int j0 = jt * 32, b0 = bt * 32;
    const int tid = threadIdx.x;
    const int x = tid & 7;                    // j-thread: 4 consecutive j
    const int y = tid >> 3;                   // b (0..31)
    const int jj = x * 4;

    // Load weight slices, transposed: WT[k][j] = W[(j0+j)*512 + k]
    {
        const int j  = tid >> 3;
        const int kc = tid & 7;
        #pragma unroll
        for (int kk = 0; kk < 16; kk++) {
            int k = (kc + kk * 8) * 4;
            float4 wc = *(const float4*)&Wc[(size_t)(j0 + j) * HID + k];
            float4 wa = *(const float4*)&Wa[(size_t)(j0 + j) * HID + k];
            WcT[(k + 0) * 32 + j] = wc.x; WcT[(k + 1) * 32 + j] = wc.y;
            WcT[(k + 2) * 32 + j] = wc.z; WcT[(k + 3) * 32 + j] = wc.w;
            WaT[(k + 0) * 32 + j] = wa.x; WaT[(k + 1) * 32 + j] = wa.y;
            WaT[(k + 2) * 32 + j] = wa.z; WaT[(k + 3) * 32 + j] = wa.w;
        }
    }

    unsigned*          cnt = &g_cnt[bt * 32];
    volatile unsigned* gen = &g_gen[bt * 32];

    for (int t = 0; t < SEQ; t++) {
        const float* __restrict__ hsrc = (t == 0) ? h_in : g_h[t & 1];
        // Stage this batch tile's full h rows into SMEM (coalesced)
        for (int i = tid; i < 32 * 128; i += 256) {
            int r = i >> 7, c = (i & 127) << 2;
            *(float4*)&Hs[r * HSTRIDE + c] =
                *(const float4*)&hsrc[(size_t)(b0 + r) * HID + c];
        }
        __syncthreads();

        // Two matvec slices: hc = h·Wc[j,:]ᵀ, ha = h·Wa[j,:]ᵀ  (f32x2 packed over j)
        u64 aC0 = 0, aC1 = 0, aA0 = 0, aA1 = 0;
        const float* hrow = &Hs[y * HSTRIDE];
        #pragma unroll 4
        for (int k = 0; k < HID; k += 4) {
            float4 hv = *(const float4*)&hrow[k];
            float hqv[4] = {hv.x, hv.y, hv.z, hv.w};
            #pragma unroll
            for (int q = 0; q < 4; q++) {
                u64 hd = dup2(hqv[q]);
                ulonglong2 wc = *(const ulonglong2*)&WcT[(k + q) * 32 + jj];
                ulonglong2 wa = *(const ulonglong2*)&WaT[(k + q) * 32 + jj];
                fma2(aC0, hd, wc.x); fma2(aC1, hd, wc.y);
                fma2(aA0, hd, wa.x); fma2(aA1, hd, wa.y);
            }
        }

        // Gated elementwise update
        const int bg = b0 + y;
        const int jg = j0 + jj;
        const size_t row = (size_t)t * BATCH + bg;
        const float* xp = &g_xp[row * 1536];
        float4 xc = *(const float4*)&xp[jg];
        float4 xa = *(const float4*)&xp[512 + jg];
        float4 xh = *(const float4*)&xp[1024 + jg];
        float2 c01 = upk(aC0), c23 = upk(aC1);
        float2 a01 = upk(aA0), a23 = upk(aA1);
        float hcv[4] = {c01.x, c01.y, c23.x, c23.y};
        float hav[4] = {a01.x, a01.y, a23.x, a23.y};
        float xcv[4] = {xc.x, xc.y, xc.z, xc.w};
        float xav[4] = {xa.x, xa.y, xa.z, xa.w};
        float xhv[4] = {xh.x, xh.y, xh.z, xh.w};
        float rr[4];
        #pragma unroll
        for (int q = 0; q < 4; q++) {
            float hp = Hs[y * HSTRIDE + jg + q];
            float cg = 1.0f / (1.0f + expf(-(xcv[q] + hcv[q])));
            float ag = 1.0f + tanhf(xav[q] + hav[q]);
            rr[q] = cg * hp + (1.0f - cg) * tanhf(xhv[q] + ag * hp);
        }
        float4 r4 = make_float4(rr[0], rr[1], rr[2], rr[3]);
        *(float4*)&out[row * HID + jg] = r4;                               // y_seq[t]
        *(float4*)&g_h[(t + 1) & 1][(size_t)bg * HID + jg] = r4;           // next h
        if (t == SEQ - 1)
            *(float4*)&out[(size_t)SEQ * BATCH * HID + (size_t)bg * HID + jg] = r4;  // hn

        // 16-way barrier among CTAs sharing this batch tile
        __threadfence();
        __syncthreads();
        if (tid == 0) {
            unsigned g = *gen;
            if (atomicAdd(cnt, 1u) == 15u) {
                atomicExch(cnt, 0u);
                __threadfence();
                *gen = g + 1;
            } else {
                while (*gen == g) __nanosleep(40);
                __threadfence();
            }
        }
        __syncthreads();
    }
}

// ============================================================================
extern "C" void kernel_launch(void* const* d_in, const int* in_sizes, int n_in,
                              void* d_out, int out_size)
{
    const float* X  = (const float*)d_in[0];
    const float* h0 = (const float*)d_in[1];
    const float* Uc = (const float*)d_in[2];
    const float* Wc = (const float*)d_in[3];
    const float* bc = (const float*)d_in[4];
    const float* Ua = (const float*)d_in[5];
    const float* Wa = (const float*)d_in[6];
    const float* ba = (const float*)d_in[7];
    const float* Uh = (const float*)d_in[8];
    const float* bh = (const float*)d_in[9];
    float* out = (float*)d_out;

    const size_t shmem = (size_t)(2 * 512 * 32 + 32 * HSTRIDE) * sizeof(float); // 197120 B
    cudaFuncSetAttribute(recur_kernel, cudaFuncAttributeMaxDynamicSharedMemorySize,
                         (int)shmem);

    dim3 pg(12, 1024);
    proj_kernel<<<pg, 256>>>(X, Uc, bc, Ua, ba, Uh, bh);
    recur_kernel<<<128, 256, shmem>>>(h0, Wc, Wa, out);
}

// round 2
// speedup vs baseline: 1.3129x; 1.3129x over previous
#include <cuda_runtime.h>
#include <cstddef>
#include <cstdint>
#include <math.h>

#define SEQ   512
#define BATCH 256
#define INP   256
#define HID   512

typedef unsigned long long u64;

// ---------- packed f32x2 helpers (sm_103a) ----------
__device__ __forceinline__ u64 dup2(float x) {
    u64 r; asm("mov.b64 %0,{%1,%1};" : "=l"(r) : "f"(x)); return r;
}
__device__ __forceinline__ void fma2(u64& d, u64 a, u64 b) {
    asm("fma.rn.f32x2 %0,%1,%2,%0;" : "+l"(d) : "l"(a), "l"(b));
}
__device__ __forceinline__ float2 upk(u64 v) {
    float2 f; asm("mov.b64 {%0,%1},%2;" : "=f"(f.x), "=f"(f.y) : "l"(v)); return f;
}

// ---------- scratch (device globals: allocation-free) ----------
__device__ float g_xp[(size_t)SEQ * BATCH * 3 * HID];   // input projections
__device__ float g_h[2][BATCH * HID];                   // double-buffered hidden state
__device__ unsigned          g_cnt[8 * 32];             // per-batch-tile barrier counters
__device__ volatile unsigned g_gen[8 * 32];             // per-batch-tile barrier generations

// ============================================================================
// Projection GEMM (unchanged from R1): XP = X @ U^T + b for 3 weight sets.
// ============================================================================
__global__ void __launch_bounds__(256) proj_kernel(
    const float* __restrict__ X,
    const float* __restrict__ Uc, const float* __restrict__ bc,
    const float* __restrict__ Ua, const float* __restrict__ ba,
    const float* __restrict__ Uh, const float* __restrict__ bh)
{
    __shared__ __align__(16) float As[16][128];
    __shared__ __align__(16) float Bs[16][128];

    const int nt = blockIdx.x;
    const int mt = blockIdx.y;
    const int n0 = nt * 128, m0 = mt * 128;
    const int region = n0 >> 9;
    const float* __restrict__ U    = (region == 0) ? Uc : (region == 1 ? Ua : Uh);
    const float* __restrict__ bias = (region == 0) ? bc : (region == 1 ? ba : bh);
    const int nl0 = n0 & 511;

    const int tid = threadIdx.x;
    const int tn = tid & 15;
    const int tm = tid >> 4;
    const int lr = tid & 127;
    const int lc = tid >> 7;

    u64 acc[8][4];
    #pragma unroll
    for (int i = 0; i < 8; i++)
        #pragma unroll
        for (int q = 0; q < 4; q++) acc[i][q] = 0ull;

    for (int kt = 0; kt < 16; kt++) {
        const int k0 = kt * 16;
        #pragma unroll
        for (int half = 0; half < 2; half++) {
            int c = lc + 2 * half;
            float4 v = *(const float4*)&X[(size_t)(m0 + lr) * INP + k0 + c * 4];
            As[c * 4 + 0][lr] = v.x; As[c * 4 + 1][lr] = v.y;
            As[c * 4 + 2][lr] = v.z; As[c * 4 + 3][lr] = v.w;
        }
        #pragma unroll
        for (int half = 0; half < 2; half++) {
            int c = lc + 2 * half;
            float4 v = *(const float4*)&U[(size_t)(nl0 + lr) * INP + k0 + c * 4];
            Bs[c * 4 + 0][lr] = v.x; Bs[c * 4 + 1][lr] = v.y;
            Bs[c * 4 + 2][lr] = v.z; Bs[c * 4 + 3][lr] = v.w;
        }
        __syncthreads();

        #pragma unroll
        for (int k = 0; k < 16; k++) {
            float4 a0 = *(const float4*)&As[k][tm * 8];
            float4 a1 = *(const float4*)&As[k][tm * 8 + 4];
            ulonglong2 b0 = *(const ulonglong2*)&Bs[k][tn * 8];
            ulonglong2 b1 = *(const ulonglong2*)&Bs[k][tn * 8 + 4];
            u64 ad[8];
            ad[0] = dup2(a0.x); ad[1] = dup2(a0.y); ad[2] = dup2(a0.z); ad[3] = dup2(a0.w);
            ad[4] = dup2(a1.x); ad[5] = dup2(a1.y); ad[6] = dup2(a1.z); ad[7] = dup2(a1.w);
            #pragma unroll
            for (int i = 0; i < 8; i++) {
                fma2(acc[i][0], ad[i], b0.x);
                fma2(acc[i][1], ad[i], b0.y);
                fma2(acc[i][2], ad[i], b1.x);
                fma2(acc[i][3], ad[i], b1.y);
            }
        }
        __syncthreads();
    }

    float bv[8];
    #pragma unroll
    for (int q = 0; q < 8; q++) bv[q] = bias[nl0 + tn * 8 + q];
    #pragma unroll
    for (int i = 0; i < 8; i++) {
        const size_t m = (size_t)m0 + tm * 8 + i;
        float2 p0 = upk(acc[i][0]), p1 = upk(acc[i][1]);
        float2 p2 = upk(acc[i][2]), p3 = upk(acc[i][3]);
        float4 o0 = make_float4(p0.x + bv[0], p0.y + bv[1], p1.x + bv[2], p1.y + bv[3]);
        float4 o1 = make_float4(p2.x + bv[4], p2.y + bv[5], p3.x + bv[6], p3.y + bv[7]);
        float* dst = &g_xp[m * 1536 + n0 + tn * 8];
        *(float4*)dst       = o0;
        *(float4*)(dst + 4) = o1;
    }
}

// ============================================================================
// Recurrence v2: warp = 32 batch rows (lane=b), each warp owns 4 j columns.
// Weight LDS loads are warp-uniform -> broadcast (1 wavefront), cutting SMEM
// crossbar traffic ~7x. Output tile staged in SMEM for coalesced stores.
// ============================================================================
#define HSTR 516        // padded h row stride (floats)
#define YSTR 36         // padded output-tile row stride (floats)

__global__ void __launch_bounds__(256) recur_kernel(
    const float* __restrict__ h_in,
    const float* __restrict__ Wc, const float* __restrict__ Wa,
    float* __restrict__ out)
{
    extern __shared__ float sm[];
    float* Wsc = sm;                      // [8 warps][512 k][4 j] = 16384
    float* Wsa = sm + 16384;              // 16384
    float* Hs  = sm + 32768;              // [32 b][HSTR]         = 16512
    float* Ys  = sm + 32768 + 16512;      // [32 b][YSTR]         = 1152

    const int ct = blockIdx.x;            // 0..127
    const int jt = ct & 15, bt = ct >> 4;
    const int j0 = jt * 32, b0 = bt * 32;
    const int tid = threadIdx.x;
    const int w = tid >> 5;               // warp id = j group (4 j)
    const int lane = tid & 31;            // batch row within tile

    // Stage weight slices: Ws[mat][w][k][jq] = W[(j0 + 4w + jq)*512 + k]
    for (int i = tid; i < 32 * 128; i += 256) {
        int j = i >> 7, kq = i & 127, k = kq * 4;
        float4 wc = *(const float4*)&Wc[(size_t)(j0 + j) * HID + k];
        float4 wa = *(const float4*)&Wa[(size_t)(j0 + j) * HID + k];
        int base = (j >> 2) * 2048 + (j & 3);
        Wsc[base + (k + 0) * 4] = wc.x; Wsc[base + (k + 1) * 4] = wc.y;
        Wsc[base + (k + 2) * 4] = wc.z; Wsc[base + (k + 3) * 4] = wc.w;
        Wsa[base + (k + 0) * 4] = wa.x; Wsa[base + (k + 1) * 4] = wa.y;
        Wsa[base + (k + 2) * 4] = wa.z; Wsa[base + (k + 3) * 4] = wa.w;
    }

    unsigned*          cnt = &g_cnt[bt * 32];
    volatile unsigned* gen = &g_gen[bt * 32];

    const float* __restrict__ wcw = &Wsc[w * 2048];
    const float* __restrict__ waw = &Wsa[w * 2048];
    const int jg = j0 + w * 4;            // this thread's 4 global j columns

    for (int t = 0; t < SEQ; t++) {
        const float* __restrict__ hsrc = (t == 0) ? h_in : g_h[t & 1];
        // Stage batch tile of h into SMEM: Hs[b][k]
        for (int i = tid; i < 32 * 128; i += 256) {
            int r = i >> 7, c = (i & 127) << 2;
            *(float4*)&Hs[r * HSTR + c] =
                *(const float4*)&hsrc[(size_t)(b0 + r) * HID + c];
        }
        __syncthreads();

        // Prefetch this step's input projections (overlap with matvec)
        const int bg = b0 + lane;
        const size_t row = (size_t)t * BATCH + bg;
        const float* __restrict__ xp = &g_xp[row * 1536];
        float4 xc = *(const float4*)&xp[jg];
        float4 xa = *(const float4*)&xp[512 + jg];
        float4 xh = *(const float4*)&xp[1024 + jg];

        // Matvec: 4 j (packed as 2 fma2 accs per matrix), weight loads broadcast
        u64 aC0 = 0, aC1 = 0, aA0 = 0, aA1 = 0;
        const float* __restrict__ hrow = &Hs[lane * HSTR];
        #pragma unroll 4
        for (int k = 0; k < HID; k += 4) {
            float4 hv = *(const float4*)&hrow[k];
            float hq[4] = {hv.x, hv.y, hv.z, hv.w};
            #pragma unroll
            for (int q = 0; q < 4; q++) {
                u64 hd = dup2(hq[q]);
                ulonglong2 wc = *(const ulonglong2*)&wcw[(k + q) * 4];
                ulonglong2 wa = *(const ulonglong2*)&waw[(k + q) * 4];
                fma2(aC0, hd, wc.x); fma2(aC1, hd, wc.y);
                fma2(aA0, hd, wa.x); fma2(aA1, hd, wa.y);
            }
        }

        // Gated elementwise update
        float4 hp4 = *(const float4*)&hrow[jg];
        float hps[4] = {hp4.x, hp4.y, hp4.z, hp4.w};
        float2 c01 = upk(aC0), c23 = upk(aC1);
        float2 a01 = upk(aA0), a23 = upk(aA1);
        float hcv[4] = {c01.x, c01.y, c23.x, c23.y};
        float hav[4] = {a01.x, a01.y, a23.x, a23.y};
        float xcv[4] = {xc.x, xc.y, xc.z, xc.w};
        float xav[4] = {xa.x, xa.y, xa.z, xa.w};
        float xhv[4] = {xh.x, xh.y, xh.z, xh.w};
        float rr[4];
        #pragma unroll
        for (int q = 0; q < 4; q++) {
            float cg = 1.0f / (1.0f + expf(-(xcv[q] + hcv[q])));
            float ag = 1.0f + tanhf(xav[q] + hav[q]);
            rr[q] = cg * hps[q] + (1.0f - cg) * tanhf(xhv[q] + ag * hps[q]);
        }
        *(float4*)&Ys[lane * YSTR + w * 4] = make_float4(rr[0], rr[1], rr[2], rr[3]);
        __syncthreads();

        // Coalesced copy-out of the 32x32 tile: y_seq[t], next h, (t=last: hn)
        {
            int r = tid >> 3;              // 0..31
            int c = (tid & 7) << 2;        // 0..28
            float4 v = *(const float4*)&Ys[r * YSTR + c];
            size_t orow = (size_t)t * BATCH + b0 + r;
            *(float4*)&out[orow * HID + j0 + c] = v;
            *(float4*)&g_h[(t + 1) & 1][(size_t)(b0 + r) * HID + j0 + c] = v;
            if (t == SEQ - 1)
                *(float4*)&out[(size_t)SEQ * BATCH * HID +
                               (size_t)(b0 + r) * HID + j0 + c] = v;
        }

        // 16-way barrier among CTAs sharing this batch tile
        __threadfence();
        __syncthreads();
        if (t < SEQ - 1) {
            if (tid == 0) {
                unsigned g = *gen;
                if (atomicAdd(cnt, 1u) == 15u) {
                    atomicExch(cnt, 0u);
                    __threadfence();
                    *gen = g + 1;
                } else {
                    while (*gen == g) __nanosleep(40);
                    __threadfence();
                }
            }
            __syncthreads();
        }
    }
}

// ============================================================================
extern "C" void kernel_launch(void* const* d_in, const int* in_sizes, int n_in,
                              void* d_out, int out_size)
{
    const float* X  = (const float*)d_in[0];
    const float* h0 = (const float*)d_in[1];
    const float* Uc = (const float*)d_in[2];
    const float* Wc = (const float*)d_in[3];
    const float* bc = (const float*)d_in[4];
    const float* Ua = (const float*)d_in[5];
    const float* Wa = (const float*)d_in[6];
    const float* ba = (const float*)d_in[7];
    const float* Uh = (const float*)d_in[8];
    const float* bh = (const float*)d_in[9];
    float* out = (float*)d_out;

    const size_t shmem = (size_t)(16384 * 2 + 32 * HSTR + 32 * YSTR) * sizeof(float); // 201728 B
    cudaFuncSetAttribute(recur_kernel, cudaFuncAttributeMaxDynamicSharedMemorySize,
                         (int)shmem);

    dim3 pg(12, 1024);
    proj_kernel<<<pg, 256>>>(X, Uc, bc, Ua, ba, Uh, bh);
    recur_kernel<<<128, 256, shmem>>>(h0, Wc, Wa, out);
}